// round 2
// baseline (speedup 1.0000x reference)
#include <cuda_runtime.h>
#include <math.h>
#include <stdint.h>

#define N_NODES    50000
#define N_EDGES    600000
#define DIM        128
#define NUM_GRAPHS 512
#define WPAD       132   // padded row stride (16B-aligned rows, conflict-free)
#define GRID_FUSED 148   // persistent blocks (one per SM)

// Scratch (device globals: allocation inside kernel_launch is forbidden)
__device__ __align__(16) float g_agg[N_NODES * DIM];
__device__ float g_deg[N_NODES];
__device__ int   g_seg[NUM_GRAPHS];

// ---------------------------------------------------------------------------
// K0: zero agg + deg
// ---------------------------------------------------------------------------
__global__ void zero_kernel() {
    int i = blockIdx.x * blockDim.x + threadIdx.x;
    int stride = gridDim.x * blockDim.x;
    float4* p = reinterpret_cast<float4*>(g_agg);
    const int n4 = N_NODES * DIM / 4;
    for (int k = i; k < n4; k += stride) p[k] = make_float4(0.f, 0.f, 0.f, 0.f);
    for (int k = i; k < N_NODES; k += stride) g_deg[k] = 0.f;
}

// ---------------------------------------------------------------------------
// K1: segment starts from the sorted batch vector
// ---------------------------------------------------------------------------
__global__ void seg_kernel(const int* __restrict__ batch) {
    int i = blockIdx.x * blockDim.x + threadIdx.x;
    int stride = gridDim.x * blockDim.x;
    for (; i < N_NODES; i += stride) {
        if (i == 0 || batch[i] != batch[i - 1]) g_seg[batch[i]] = i;
    }
}

// ---------------------------------------------------------------------------
// K2: edge scatter. One warp per edge: gather emb[x_ids[src]] row (512B,
// coalesced), vector-reduce into agg[dst]. deg counted by lane 0.
// emb (10MB) + agg (25.6MB) are L2-resident -> L2/atomic-throughput bound.
// ---------------------------------------------------------------------------
__global__ void scatter_kernel(const int* __restrict__ ei,
                               const int* __restrict__ xids,
                               const float* __restrict__ emb) {
    int warp = (blockIdx.x * blockDim.x + threadIdx.x) >> 5;
    int lane = threadIdx.x & 31;
    if (warp >= N_EDGES) return;
    int src = __ldg(ei + warp);            // broadcast within warp (1 sector)
    int dst = __ldg(ei + N_EDGES + warp);
    int id  = __ldg(xids + src);
    const float4* row = reinterpret_cast<const float4*>(emb + (size_t)id * DIM);
    float4 v = __ldg(row + lane);
    float* outp = g_agg + (size_t)dst * DIM + lane * 4;
    asm volatile("red.global.add.v4.f32 [%0], {%1,%2,%3,%4};"
                 :: "l"(outp), "f"(v.x), "f"(v.y), "f"(v.z), "f"(v.w)
                 : "memory");
    if (lane == 0) atomicAdd(g_deg + dst, 1.0f);
}

// ---------------------------------------------------------------------------
// K3 (persistent): deg-normalize -> dual GEMM -> relu -> segment max/mean
// pool -> final linear -> sigmoid. 148 blocks x 128 threads; block loops over
// graphs bid, bid+148, ... Thread t owns output column t. Weights loaded into
// shared ONCE per block (stride-132 pad: 16B-aligned rows, conflict-free
// float4 reads). Nodes processed 4 at a time with register double-buffering.
// ---------------------------------------------------------------------------
__global__ void __launch_bounds__(128, 1)
fused_kernel(const int* __restrict__ xids,
             const float* __restrict__ emb,
             const float* __restrict__ Wl,
             const float* __restrict__ bl,
             const float* __restrict__ Wr,
             const float* __restrict__ w1,
             const float* __restrict__ b1,
             float* __restrict__ out) {
    extern __shared__ float sm[];
    float*  sWl  = sm;                         // [128][132]
    float*  sWr  = sm + DIM * WPAD;            // [128][132]
    float4* sA   = reinterpret_cast<float4*>(sm + 2 * DIM * WPAD); // [2][128]
    float4* sX   = sA + 2 * DIM;                                    // [2][128]
    float*  sred = reinterpret_cast<float*>(sX + 2 * DIM);          // [4]

    const int t = threadIdx.x;

    // Load weights once: coalesced global reads, conflict-free shared stores.
    for (int idx = t; idx < DIM * DIM; idx += 128) {
        int j = idx >> 7, k = idx & 127;
        sWl[j * WPAD + k] = Wl[idx];
        sWr[j * WPAD + k] = Wr[idx];
    }
    __syncthreads();

    const float blj = bl[t];
    const float w1a = w1[t];
    const float w1b = w1[DIM + t];
    const float4* wlrow4 = reinterpret_cast<const float4*>(sWl + t * WPAD);
    const float4* wrrow4 = reinterpret_cast<const float4*>(sWr + t * WPAD);

    for (int g = blockIdx.x; g < NUM_GRAPHS; g += GRID_FUSED) {
        const int start = g_seg[g];
        const int end   = (g == NUM_GRAPHS - 1) ? N_NODES : g_seg[g + 1];
        const int cnt   = end - start;

        float maxj = 0.f;   // relu >= 0, so 0 is a valid max identity
        float sumj = 0.f;

        float pA[4], pX[4];
        auto prefetch = [&](int base) {
#pragma unroll
            for (int m = 0; m < 4; m++) {
                int n = base + m;
                if (n < end) {
                    float sc = 1.f / fmaxf(g_deg[n], 1.f);
                    pA[m] = g_agg[(size_t)n * DIM + t] * sc;
                    pX[m] = emb[(size_t)__ldg(xids + n) * DIM + t];
                } else {
                    pA[m] = 0.f; pX[m] = 0.f;
                }
            }
        };

        prefetch(start);
        int buf = 0;
        for (int base = start; base < end; base += 4) {
            sA[buf * DIM + t] = make_float4(pA[0], pA[1], pA[2], pA[3]);
            sX[buf * DIM + t] = make_float4(pX[0], pX[1], pX[2], pX[3]);
            __syncthreads();
            prefetch(base + 4);          // overlap next-group LDGs with FMAs

            float aL0 = 0.f, aL1 = 0.f, aL2 = 0.f, aL3 = 0.f;
            float aR0 = 0.f, aR1 = 0.f, aR2 = 0.f, aR3 = 0.f;
            const float4* inA = sA + buf * DIM;
            const float4* inX = sX + buf * DIM;
#pragma unroll 8
            for (int kq = 0; kq < DIM / 4; kq++) {
                float4 wL = wlrow4[kq];
                float4 wR = wrrow4[kq];
#pragma unroll
                for (int i = 0; i < 4; i++) {
                    float wl = (i == 0) ? wL.x : (i == 1) ? wL.y : (i == 2) ? wL.z : wL.w;
                    float wr = (i == 0) ? wR.x : (i == 1) ? wR.y : (i == 2) ? wR.z : wR.w;
                    float4 a = inA[kq * 4 + i];   // 16B broadcast LDS
                    float4 x = inX[kq * 4 + i];
                    aL0 = fmaf(a.x, wl, aL0); aL1 = fmaf(a.y, wl, aL1);
                    aL2 = fmaf(a.z, wl, aL2); aL3 = fmaf(a.w, wl, aL3);
                    aR0 = fmaf(x.x, wr, aR0); aR1 = fmaf(x.y, wr, aR1);
                    aR2 = fmaf(x.z, wr, aR2); aR3 = fmaf(x.w, wr, aR3);
                }
            }

            float hv;
            if (base + 0 < end) { hv = fmaxf(aL0 + aR0 + blj, 0.f); maxj = fmaxf(maxj, hv); sumj += hv; }
            if (base + 1 < end) { hv = fmaxf(aL1 + aR1 + blj, 0.f); maxj = fmaxf(maxj, hv); sumj += hv; }
            if (base + 2 < end) { hv = fmaxf(aL2 + aR2 + blj, 0.f); maxj = fmaxf(maxj, hv); sumj += hv; }
            if (base + 3 < end) { hv = fmaxf(aL3 + aR3 + blj, 0.f); maxj = fmaxf(maxj, hv); sumj += hv; }
            buf ^= 1;
        }

        // pooled = [hmax, hmean];  per-thread contribution, then block-reduce
        float val = maxj * w1a + (sumj / (float)cnt) * w1b;
#pragma unroll
        for (int off = 16; off > 0; off >>= 1)
            val += __shfl_down_sync(0xFFFFFFFFu, val, off);
        if ((t & 31) == 0) sred[t >> 5] = val;
        __syncthreads();
        if (t == 0) {
            float tot = sred[0] + sred[1] + sred[2] + sred[3] + b1[0];
            out[g] = 1.f / (1.f + expf(-tot));
        }
        __syncthreads();   // protect sred before next graph
    }
}

// ---------------------------------------------------------------------------
extern "C" void kernel_launch(void* const* d_in, const int* in_sizes, int n_in,
                              void* d_out, int out_size) {
    const int*   xids  = (const int*)d_in[0];
    const int*   ei    = (const int*)d_in[1];
    const int*   batch = (const int*)d_in[2];
    const float* emb   = (const float*)d_in[3];
    const float* Wl    = (const float*)d_in[4];
    const float* bl    = (const float*)d_in[5];
    const float* Wr    = (const float*)d_in[6];
    const float* w1    = (const float*)d_in[7];
    const float* b1    = (const float*)d_in[8];
    float*       out   = (float*)d_out;

    zero_kernel<<<2048, 256>>>();
    seg_kernel<<<256, 256>>>(batch);
    {
        long long threads = (long long)N_EDGES * 32;
        int blocks = (int)((threads + 255) / 256);
        scatter_kernel<<<blocks, 256>>>(ei, xids, emb);
    }
    size_t smem = (2 * DIM * WPAD + 2 * DIM * 4 + 2 * DIM * 4 + 4) * sizeof(float);
    static int attr_set = 0;
    if (!attr_set) {
        cudaFuncSetAttribute(fused_kernel,
                             cudaFuncAttributeMaxDynamicSharedMemorySize, (int)smem);
        attr_set = 1;
    }
    fused_kernel<<<GRID_FUSED, 128, smem>>>(xids, emb, Wl, bl, Wr, w1, b1, out);
}

// round 3
// speedup vs baseline: 1.3770x; 1.3770x over previous
#include <cuda_runtime.h>
#include <math.h>
#include <stdint.h>

#define N_NODES    50000
#define N_EDGES    600000
#define DIM        128
#define NUM_GRAPHS 512
#define GRID_FUSED 148      // persistent blocks (one per SM)
#define WSTRIDE    260      // floats per combined-weight row (1040 B: 16B-aligned, conflict-free)

// Scratch (device globals: allocation inside kernel_launch is forbidden)
__device__ __align__(16) float g_agg[N_NODES * DIM];
__device__ float g_deg[N_NODES];
__device__ int   g_seg[NUM_GRAPHS];

// ---- packed f32x2 helpers (sm_100a) ---------------------------------------
#define FMA2(acc, lo, hi, w) do {                                          \
    unsigned long long _ab;                                                \
    asm("mov.b64 %0, {%1, %2};" : "=l"(_ab) : "f"(lo), "f"(hi));           \
    asm("fma.rn.f32x2 %0, %1, %2, %0;" : "+l"(acc) : "l"(_ab), "l"(w));    \
} while (0)
#define PACK2(d, lo, hi) \
    asm("mov.b64 %0, {%1, %2};" : "=l"(d) : "f"(lo), "f"(hi))
#define UNPACK2(lo, hi, v) \
    asm("mov.b64 {%0, %1}, %2;" : "=f"(lo), "=f"(hi) : "l"(v))

// ---------------------------------------------------------------------------
// K0: zero agg + deg
// ---------------------------------------------------------------------------
__global__ void zero_kernel() {
    int i = blockIdx.x * blockDim.x + threadIdx.x;
    int stride = gridDim.x * blockDim.x;
    float4* p = reinterpret_cast<float4*>(g_agg);
    const int n4 = N_NODES * DIM / 4;
    for (int k = i; k < n4; k += stride) p[k] = make_float4(0.f, 0.f, 0.f, 0.f);
    for (int k = i; k < N_NODES; k += stride) g_deg[k] = 0.f;
}

// ---------------------------------------------------------------------------
// K1: segment starts from the sorted batch vector
// ---------------------------------------------------------------------------
__global__ void seg_kernel(const int* __restrict__ batch) {
    int i = blockIdx.x * blockDim.x + threadIdx.x;
    int stride = gridDim.x * blockDim.x;
    for (; i < N_NODES; i += stride) {
        if (i == 0 || batch[i] != batch[i - 1]) g_seg[batch[i]] = i;
    }
}

// ---------------------------------------------------------------------------
// K2: edge scatter. One warp per edge: gather emb[x_ids[src]] row (512B,
// coalesced), vector-reduce into agg[dst]. deg counted by lane 0.
// ---------------------------------------------------------------------------
__global__ void scatter_kernel(const int* __restrict__ ei,
                               const int* __restrict__ xids,
                               const float* __restrict__ emb) {
    int warp = (blockIdx.x * blockDim.x + threadIdx.x) >> 5;
    int lane = threadIdx.x & 31;
    if (warp >= N_EDGES) return;
    int src = __ldg(ei + warp);
    int dst = __ldg(ei + N_EDGES + warp);
    int id  = __ldg(xids + src);
    const float4* row = reinterpret_cast<const float4*>(emb + (size_t)id * DIM);
    float4 v = __ldg(row + lane);
    float* outp = g_agg + (size_t)dst * DIM + lane * 4;
    asm volatile("red.global.add.v4.f32 [%0], {%1,%2,%3,%4};"
                 :: "l"(outp), "f"(v.x), "f"(v.y), "f"(v.z), "f"(v.w)
                 : "memory");
    if (lane == 0) atomicAdd(g_deg + dst, 1.0f);
}

// ---------------------------------------------------------------------------
// K3 (persistent, 512 thr): deg-normalize -> dual GEMM (packed f32x2) ->
// relu -> segment max/mean pool -> final linear -> sigmoid.
// Thread (r,c): r = row-group 0..3 (4 nodes each => 16 nodes/iter), c = column.
// Weights stored interleaved (Wl,Wr) pairs; node data staged as (agg,x) pairs
// so fma.rn.f32x2 computes both GEMMs in one instruction stream.
// ---------------------------------------------------------------------------
__global__ void __launch_bounds__(512, 1)
fused_kernel(const int* __restrict__ xids,
             const float* __restrict__ emb,
             const float* __restrict__ Wl,
             const float* __restrict__ bl,
             const float* __restrict__ Wr,
             const float* __restrict__ w1,
             const float* __restrict__ b1,
             float* __restrict__ out) {
    extern __shared__ float sm[];
    float*  sWc  = sm;                                        // [128][260]
    float4* sAX4 = reinterpret_cast<float4*>(sm + DIM * WSTRIDE); // [2][4][128][2] float4
    float*  sMax = sm + DIM * WSTRIDE + 8192;                 // [4][128]
    float*  sSum = sMax + 512;                                // [4][128]
    float*  sred = sSum + 512;                                // [4]

    const int t = threadIdx.x;
    const int r = t >> 7;       // row group 0..3
    const int c = t & 127;      // output column

    // Build combined weight tile: sWc[j][2k] = Wl[j][k], sWc[j][2k+1] = Wr[j][k]
    for (int idx = t; idx < DIM * DIM; idx += 512) {
        int j = idx >> 7, k = idx & 127;
        sWc[j * WSTRIDE + 2 * k]     = Wl[idx];
        sWc[j * WSTRIDE + 2 * k + 1] = Wr[idx];
    }
    __syncthreads();

    const float blj = bl[c];
    const float w1a = w1[c];
    const float w1b = w1[DIM + c];
    const float4* wrow4 = reinterpret_cast<const float4*>(sWc + c * WSTRIDE);

    for (int g = blockIdx.x; g < NUM_GRAPHS; g += GRID_FUSED) {
        const int start = g_seg[g];
        const int end   = (g == NUM_GRAPHS - 1) ? N_NODES : g_seg[g + 1];
        const int cnt   = end - start;

        float maxj = 0.f;   // relu >= 0: 0 is a valid max identity
        float sumj = 0.f;

        float pA[4], pX[4];
        auto prefetch = [&](int base) {
#pragma unroll
            for (int m = 0; m < 4; m++) {
                int n = base + r * 4 + m;
                if (n < end) {
                    float sc = __fdividef(1.f, fmaxf(g_deg[n], 1.f));
                    pA[m] = g_agg[(size_t)n * DIM + c] * sc;
                    pX[m] = emb[(size_t)__ldg(xids + n) * DIM + c];
                } else {
                    pA[m] = 0.f; pX[m] = 0.f;
                }
            }
        };

        prefetch(start);
        int buf = 0;
        for (int base = start; base < end; base += 16) {
            // publish this row-group's 4 nodes as (a,x) pairs, indexed by feature c
            float4* axw = sAX4 + (size_t)(buf * 4 + r) * 256;
            axw[c * 2]     = make_float4(pA[0], pX[0], pA[1], pX[1]);
            axw[c * 2 + 1] = make_float4(pA[2], pX[2], pA[3], pX[3]);
            __syncthreads();
            prefetch(base + 16);                 // overlap next-group LDGs

            const float4* axr = sAX4 + (size_t)(buf * 4 + r) * 256;
            unsigned long long A0 = 0, A1 = 0, A2 = 0, A3 = 0;
#pragma unroll 8
            for (int kk = 0; kk < DIM / 2; kk++) {      // 2 features per kk
                float4 w4 = wrow4[kk];                  // (wl_k, wr_k, wl_k1, wr_k1)
                unsigned long long w2a, w2b;
                PACK2(w2a, w4.x, w4.y);
                PACK2(w2b, w4.z, w4.w);
                float4 p0 = axr[kk * 4 + 0];            // k  : (a0,x0,a1,x1)
                float4 p1 = axr[kk * 4 + 1];            // k  : (a2,x2,a3,x3)
                float4 p2 = axr[kk * 4 + 2];            // k+1: (a0,x0,a1,x1)
                float4 p3 = axr[kk * 4 + 3];            // k+1: (a2,x2,a3,x3)
                FMA2(A0, p0.x, p0.y, w2a); FMA2(A1, p0.z, p0.w, w2a);
                FMA2(A2, p1.x, p1.y, w2a); FMA2(A3, p1.z, p1.w, w2a);
                FMA2(A0, p2.x, p2.y, w2b); FMA2(A1, p2.z, p2.w, w2b);
                FMA2(A2, p3.x, p3.y, w2b); FMA2(A3, p3.z, p3.w, w2b);
            }

            // h_m = relu(aggGemm + xGemm + bias); pool with pad-node predicates
            float lo, hi, hv;
            UNPACK2(lo, hi, A0);
            if (base + r * 4 + 0 < end) { hv = fmaxf(lo + hi + blj, 0.f); maxj = fmaxf(maxj, hv); sumj += hv; }
            UNPACK2(lo, hi, A1);
            if (base + r * 4 + 1 < end) { hv = fmaxf(lo + hi + blj, 0.f); maxj = fmaxf(maxj, hv); sumj += hv; }
            UNPACK2(lo, hi, A2);
            if (base + r * 4 + 2 < end) { hv = fmaxf(lo + hi + blj, 0.f); maxj = fmaxf(maxj, hv); sumj += hv; }
            UNPACK2(lo, hi, A3);
            if (base + r * 4 + 3 < end) { hv = fmaxf(lo + hi + blj, 0.f); maxj = fmaxf(maxj, hv); sumj += hv; }
            buf ^= 1;
        }

        // combine the 4 row-groups, then final linear + sigmoid
        sMax[r * DIM + c] = maxj;
        sSum[r * DIM + c] = sumj;
        __syncthreads();
        if (r == 0) {
            float M = fmaxf(fmaxf(sMax[c], sMax[DIM + c]),
                            fmaxf(sMax[2 * DIM + c], sMax[3 * DIM + c]));
            float S = sSum[c] + sSum[DIM + c] + sSum[2 * DIM + c] + sSum[3 * DIM + c];
            float val = M * w1a + (S / (float)cnt) * w1b;
#pragma unroll
            for (int off = 16; off > 0; off >>= 1)
                val += __shfl_down_sync(0xFFFFFFFFu, val, off);
            if ((c & 31) == 0) sred[c >> 5] = val;
        }
        __syncthreads();
        if (t == 0) {
            float tot = sred[0] + sred[1] + sred[2] + sred[3] + b1[0];
            out[g] = 1.f / (1.f + expf(-tot));
        }
        __syncthreads();    // protect sred/sMax/sSum before next graph
    }
}

// ---------------------------------------------------------------------------
extern "C" void kernel_launch(void* const* d_in, const int* in_sizes, int n_in,
                              void* d_out, int out_size) {
    const int*   xids  = (const int*)d_in[0];
    const int*   ei    = (const int*)d_in[1];
    const int*   batch = (const int*)d_in[2];
    const float* emb   = (const float*)d_in[3];
    const float* Wl    = (const float*)d_in[4];
    const float* bl    = (const float*)d_in[5];
    const float* Wr    = (const float*)d_in[6];
    const float* w1    = (const float*)d_in[7];
    const float* b1    = (const float*)d_in[8];
    float*       out   = (float*)d_out;

    zero_kernel<<<2048, 256>>>();
    seg_kernel<<<256, 256>>>(batch);
    {
        long long threads = (long long)N_EDGES * 32;
        int blocks = (int)((threads + 255) / 256);
        scatter_kernel<<<blocks, 256>>>(ei, xids, emb);
    }
    // smem: weights 128*260 + staging 8192 + pool 1024 + sred 4 floats
    size_t smem = (size_t)(DIM * WSTRIDE + 8192 + 1024 + 4) * sizeof(float);
    static int attr_set = 0;
    if (!attr_set) {
        cudaFuncSetAttribute(fused_kernel,
                             cudaFuncAttributeMaxDynamicSharedMemorySize, (int)smem);
        attr_set = 1;
    }
    fused_kernel<<<GRID_FUSED, 512, smem>>>(xids, emb, Wl, bl, Wr, w1, b1, out);
}